// round 3
// baseline (speedup 1.0000x reference)
#include <cuda_runtime.h>
#include <cstdint>

#define EPS 1e-5f
#define SA 130
typedef unsigned long long u64;
typedef long long i64;

// ---------------- scratch (device globals; no runtime alloc) ----------------
__device__ float S1[600000 * 128];   // h1/h (mode-major) -> dh2 -> c1
__device__ float S3[600000 * 60];    // preds, layout [n][k][60]
__device__ float S4[600000];         // cls logits
__device__ float S5[100000 * 128];   // actors @ agt_W[128:256]

// ---------------- f32x2 helpers ---------------------------------------------
__device__ __forceinline__ void fma2(u64& d, u64 a, u64 b) {
    asm("fma.rn.f32x2 %0, %1, %2, %0;" : "+l"(d) : "l"(a), "l"(b));
}
__device__ __forceinline__ u64 pk(float x) {
    u64 r; asm("mov.b64 %0, {%1, %1};" : "=l"(r) : "f"(x)); return r;
}
__device__ __forceinline__ void up(float& lo, float& hi, u64 v) {
    asm("mov.b64 {%0, %1}, %2;" : "=f"(lo), "=f"(hi) : "l"(v));
}

// ---------------- generic fused GEMM: out = epi(A[M,128] @ W[128,128]) ------
struct GP {
    const float* A;  i64 A_k;        // A row-major, per-blockIdx.y stride
    const float* W;  i64 W_k;
    const float* g;  const float* b;  i64 gb_k;
    float* out;      i64 out_k;      // may be null
    const float* pre;                // pre-GN add, row = grow/6 (or null)
    const float* post; i64 post_k;   // post-GN add, row = grow (or null)
    const float* wo; const float* wob; float* dot;  // fused dot epilogue
    const float* genP; const float* W0; const float* b0;  // dist A-gen
    int M, gn, relu;
};

__global__ void __launch_bounds__(256, 1) gemm_k(GP p) {
    extern __shared__ float sm[];
    float* As = sm;               // [128][SA] transposed A tile (k-major)
    float* Ws = As + 128 * SA;    // [128][128]
    float* gv = Ws + 16384;       // 128
    float* bv = gv + 128;         // 128
    float* wv = bv + 128;         // 128
    float* w0 = wv + 128;         // 256
    float* b0 = w0 + 256;         // 128
    float* pa = b0 + 128;         // 128
    float* pb = pa + 128;         // 128

    const int tid = threadIdx.x;
    const int y = blockIdx.y;
    const int row0 = blockIdx.x * 128;

    {   // preload W (coalesced float4)
        const float4* s = (const float4*)(p.W + p.W_k * y);
        float4* d = (float4*)Ws;
        #pragma unroll
        for (int i = 0; i < 16; i++) d[tid + 256 * i] = s[tid + 256 * i];
    }
    if (p.gn && tid < 128) { gv[tid] = p.g[p.gb_k * y + tid]; bv[tid] = p.b[p.gb_k * y + tid]; }
    if (p.wo && tid < 128) wv[tid] = p.wo[tid];

    if (p.genP) {
        // A[r][c] = relu(b0[c] - p58*W0[0][c] - p59*W0[1][c])
        if (tid < 256) w0[tid] = p.W0[tid];
        if (tid < 128) b0[tid] = p.b0[tid];
        if (tid < 128) {
            int gr = row0 + tid; float a = 0.f, bq = 0.f;
            if (gr < p.M) { a = p.genP[(size_t)gr * 60 + 58]; bq = p.genP[(size_t)gr * 60 + 59]; }
            pa[tid] = a; pb[tid] = bq;
        }
        __syncthreads();
        for (int it = 0; it < 64; it++) {
            int idx = tid + it * 256;
            int r = idx >> 7, c = idx & 127;
            As[c * SA + r] = fmaxf(b0[c] - pa[r] * w0[c] - pb[r] * w0[128 + c], 0.f);
        }
    } else {
        const float* Ag = p.A + p.A_k * y;
        #pragma unroll
        for (int it = 0; it < 16; it++) {
            int idx = tid + it * 256;
            int r = idx >> 5, c4 = (idx & 31) * 4, gr = row0 + r;
            float4 v = make_float4(0.f, 0.f, 0.f, 0.f);
            if (gr < p.M) v = *(const float4*)(Ag + (size_t)gr * 128 + c4);
            As[(c4    ) * SA + r] = v.x; As[(c4 + 1) * SA + r] = v.y;
            As[(c4 + 2) * SA + r] = v.z; As[(c4 + 3) * SA + r] = v.w;
        }
    }
    __syncthreads();

    const int rg = tid >> 4, cg = tid & 15;   // rows rg*8..+7, cols cg*8..+7
    u64 acc[4][8];
    #pragma unroll
    for (int i = 0; i < 4; i++)
        #pragma unroll
        for (int j = 0; j < 8; j++) acc[i][j] = 0ull;

    #pragma unroll 2
    for (int k = 0; k < 128; k++) {
        const u64* ap = (const u64*)(As + k * SA + rg * 8);
        u64 a0 = ap[0], a1 = ap[1], a2 = ap[2], a3 = ap[3];
        const float4* wp = (const float4*)(Ws + k * 128 + cg * 8);
        float4 q0 = wp[0], q1 = wp[1];
        u64 bb[8] = {pk(q0.x), pk(q0.y), pk(q0.z), pk(q0.w),
                     pk(q1.x), pk(q1.y), pk(q1.z), pk(q1.w)};
        #pragma unroll
        for (int j = 0; j < 8; j++) {
            fma2(acc[0][j], a0, bb[j]); fma2(acc[1][j], a1, bb[j]);
            fma2(acc[2][j], a2, bb[j]); fma2(acc[3][j], a3, bb[j]);
        }
    }

    const int cb = cg * 8;
    float* og = p.out ? p.out + p.out_k * y : nullptr;
    const float* pog = p.post ? p.post + p.post_k * y : nullptr;

    #pragma unroll 1
    for (int i = 0; i < 4; i++) {
        float lo[8], hi[8];
        #pragma unroll
        for (int j = 0; j < 8; j++) up(lo[j], hi[j], acc[i][j]);
        int rl = row0 + rg * 8 + 2 * i, rh = rl + 1;
        bool okl = rl < p.M, okh = rh < p.M;

        if (p.pre) {
            if (okl) { const float4* q = (const float4*)(p.pre + (size_t)(rl / 6) * 128 + cb);
                float4 a = q[0], c = q[1];
                lo[0]+=a.x; lo[1]+=a.y; lo[2]+=a.z; lo[3]+=a.w; lo[4]+=c.x; lo[5]+=c.y; lo[6]+=c.z; lo[7]+=c.w; }
            if (okh) { const float4* q = (const float4*)(p.pre + (size_t)(rh / 6) * 128 + cb);
                float4 a = q[0], c = q[1];
                hi[0]+=a.x; hi[1]+=a.y; hi[2]+=a.z; hi[3]+=a.w; hi[4]+=c.x; hi[5]+=c.y; hi[6]+=c.z; hi[7]+=c.w; }
        }
        if (p.gn) {
            float s0 = 0.f, q0 = 0.f, s1 = 0.f, q1 = 0.f;
            #pragma unroll
            for (int j = 0; j < 8; j++) {
                s0 += lo[j]; q0 += lo[j] * lo[j];
                s1 += hi[j]; q1 += hi[j] * hi[j];
            }
            #pragma unroll
            for (int m = 8; m >= 1; m >>= 1) {
                s0 += __shfl_xor_sync(~0u, s0, m); q0 += __shfl_xor_sync(~0u, q0, m);
                s1 += __shfl_xor_sync(~0u, s1, m); q1 += __shfl_xor_sync(~0u, q1, m);
            }
            float ml = s0 * (1.f / 128.f), mh = s1 * (1.f / 128.f);
            float il = rsqrtf(q0 * (1.f / 128.f) - ml * ml + EPS);
            float ih = rsqrtf(q1 * (1.f / 128.f) - mh * mh + EPS);
            #pragma unroll
            for (int j = 0; j < 8; j++) {
                float gg = gv[cb + j], bz = bv[cb + j];
                lo[j] = (lo[j] - ml) * il * gg + bz;
                hi[j] = (hi[j] - mh) * ih * gg + bz;
            }
        }
        if (pog) {
            if (okl) { const float4* q = (const float4*)(pog + (size_t)rl * 128 + cb);
                float4 a = q[0], c = q[1];
                lo[0]+=a.x; lo[1]+=a.y; lo[2]+=a.z; lo[3]+=a.w; lo[4]+=c.x; lo[5]+=c.y; lo[6]+=c.z; lo[7]+=c.w; }
            if (okh) { const float4* q = (const float4*)(pog + (size_t)rh * 128 + cb);
                float4 a = q[0], c = q[1];
                hi[0]+=a.x; hi[1]+=a.y; hi[2]+=a.z; hi[3]+=a.w; hi[4]+=c.x; hi[5]+=c.y; hi[6]+=c.z; hi[7]+=c.w; }
        }
        if (p.relu) {
            #pragma unroll
            for (int j = 0; j < 8; j++) { lo[j] = fmaxf(lo[j], 0.f); hi[j] = fmaxf(hi[j], 0.f); }
        }
        if (p.wo) {
            float dl = 0.f, dh = 0.f;
            #pragma unroll
            for (int j = 0; j < 8; j++) { float w = wv[cb + j]; dl += lo[j] * w; dh += hi[j] * w; }
            #pragma unroll
            for (int m = 8; m >= 1; m >>= 1) {
                dl += __shfl_xor_sync(~0u, dl, m); dh += __shfl_xor_sync(~0u, dh, m);
            }
            if (cg == 0) {
                float bz = p.wob[0];
                if (okl) p.dot[rl] = dl + bz;
                if (okh) p.dot[rh] = dh + bz;
            }
        }
        if (og) {
            if (okl) { float4* d = (float4*)(og + (size_t)rl * 128 + cb);
                d[0] = make_float4(lo[0], lo[1], lo[2], lo[3]);
                d[1] = make_float4(lo[4], lo[5], lo[6], lo[7]); }
            if (okh) { float4* d = (float4*)(og + (size_t)rh * 128 + cb);
                d[0] = make_float4(hi[0], hi[1], hi[2], hi[3]);
                d[1] = make_float4(hi[4], hi[5], hi[6], hi[7]); }
        }
    }
}

// ---------------- Wo head: [M,128] @ [128,60] + bias -> S3[n*360 + k*60] ----
__global__ void __launch_bounds__(256, 1) gemm_wo(
    const float* A, i64 A_k, const float* W, i64 W_k,
    const float* bo, float* out, int M)
{
    extern __shared__ float sm[];
    float* As = sm;               // [128][SA]
    float* Ws = As + 128 * SA;    // [128][64] (cols 60..63 zero)
    float* bb = Ws + 128 * 64;    // 64

    const int tid = threadIdx.x, y = blockIdx.y, row0 = blockIdx.x * 128;
    const float* Wg = W + W_k * y;
    out += y * 60;

    for (int idx = tid; idx < 128 * 64; idx += 256) {
        int r = idx >> 6, c = idx & 63;
        Ws[idx] = (c < 60) ? Wg[r * 60 + c] : 0.f;
    }
    if (tid < 64) bb[tid] = (tid < 60) ? bo[y * 60 + tid] : 0.f;

    const float* Ag = A + A_k * y;
    #pragma unroll
    for (int it = 0; it < 16; it++) {
        int idx = tid + it * 256;
        int r = idx >> 5, c4 = (idx & 31) * 4, gr = row0 + r;
        float4 v = make_float4(0.f, 0.f, 0.f, 0.f);
        if (gr < M) v = *(const float4*)(Ag + (size_t)gr * 128 + c4);
        As[(c4    ) * SA + r] = v.x; As[(c4 + 1) * SA + r] = v.y;
        As[(c4 + 2) * SA + r] = v.z; As[(c4 + 3) * SA + r] = v.w;
    }
    __syncthreads();

    const int rg = tid >> 4, cg = tid & 15;   // rows rg*8..+7, cols cg*4..+3
    u64 acc[4][4];
    #pragma unroll
    for (int i = 0; i < 4; i++)
        #pragma unroll
        for (int j = 0; j < 4; j++) acc[i][j] = 0ull;

    #pragma unroll 4
    for (int k = 0; k < 128; k++) {
        const u64* ap = (const u64*)(As + k * SA + rg * 8);
        u64 a0 = ap[0], a1 = ap[1], a2 = ap[2], a3 = ap[3];
        float4 q = *(const float4*)(Ws + k * 64 + cg * 4);
        u64 b0 = pk(q.x), b1 = pk(q.y), b2 = pk(q.z), b3 = pk(q.w);
        fma2(acc[0][0], a0, b0); fma2(acc[0][1], a0, b1); fma2(acc[0][2], a0, b2); fma2(acc[0][3], a0, b3);
        fma2(acc[1][0], a1, b0); fma2(acc[1][1], a1, b1); fma2(acc[1][2], a1, b2); fma2(acc[1][3], a1, b3);
        fma2(acc[2][0], a2, b0); fma2(acc[2][1], a2, b1); fma2(acc[2][2], a2, b2); fma2(acc[2][3], a2, b3);
        fma2(acc[3][0], a3, b0); fma2(acc[3][1], a3, b1); fma2(acc[3][2], a3, b2); fma2(acc[3][3], a3, b3);
    }

    #pragma unroll
    for (int i = 0; i < 4; i++) {
        int rl = row0 + rg * 8 + 2 * i, rh = rl + 1;
        #pragma unroll
        for (int j = 0; j < 4; j++) {
            int c = cg * 4 + j;
            float lo, hi; up(lo, hi, acc[i][j]);
            if (c < 60) {
                if (rl < M) out[(size_t)rl * 360 + c] = lo + bb[c];
                if (rh < M) out[(size_t)rh * 360 + c] = hi + bb[c];
            }
        }
    }
}

// ---------------- softmax + rank-sort + reg gather (warp per actor) ---------
__global__ void finalize(const float* preds, const float* lg, const float* ctr,
                         float* clsO, float* regO, int N)
{
    int w = (blockIdx.x * blockDim.x + threadIdx.x) >> 5;
    int lane = threadIdx.x & 31;
    if (w >= N) return;
    float v = (lane < 6) ? lg[(size_t)w * 6 + lane] : -3.4e38f;
    float m = v;
    #pragma unroll
    for (int s = 4; s >= 1; s >>= 1) m = fmaxf(m, __shfl_xor_sync(~0u, m, s));
    float e = (lane < 6) ? expf(v - m) : 0.f;
    float s = e;
    #pragma unroll
    for (int t = 4; t >= 1; t >>= 1) s += __shfl_xor_sync(~0u, s, t);
    float pr = e / s;
    int rk = 0;
    #pragma unroll
    for (int j = 0; j < 6; j++) {
        float pj = __shfl_sync(~0u, pr, j);
        rk += (pj > pr) || (pj == pr && j < lane);
    }
    if (lane < 6) clsO[(size_t)w * 6 + rk] = pr;
    float cx = ctr[(size_t)w * 2], cy = ctr[(size_t)w * 2 + 1];
    for (int k = 0; k < 6; k++) {
        int r = __shfl_sync(~0u, rk, k);
        const float* sp = preds + (size_t)w * 360 + k * 60;
        float* dp = regO + ((size_t)w * 6 + r) * 60;
        for (int j = lane; j < 60; j += 32) dp[j] = sp[j] + ((j & 1) ? cy : cx);
    }
}

// ---------------- host orchestration ----------------------------------------
extern "C" void kernel_launch(void* const* d_in, const int* in_sizes, int n_in,
                              void* d_out, int out_size)
{
    const float* actors = (const float*)d_in[0];
    const float* ctrs   = (const float*)d_in[1];
    const float* pW1 = (const float*)d_in[2];
    const float* pg1 = (const float*)d_in[3];
    const float* pb1 = (const float*)d_in[4];
    const float* pW2 = (const float*)d_in[5];
    const float* pg2 = (const float*)d_in[6];
    const float* pb2 = (const float*)d_in[7];
    const float* pWo = (const float*)d_in[8];
    const float* pbo = (const float*)d_in[9];
    const float* dW0 = (const float*)d_in[10];
    const float* db0 = (const float*)d_in[11];
    const float* dW1 = (const float*)d_in[12];
    const float* dg1 = (const float*)d_in[13];
    const float* db1 = (const float*)d_in[14];
    const float* aW  = (const float*)d_in[15];
    const float* ag  = (const float*)d_in[16];
    const float* ab  = (const float*)d_in[17];
    const float* cW1 = (const float*)d_in[18];
    const float* cg1 = (const float*)d_in[19];
    const float* cb1 = (const float*)d_in[20];
    const float* cW2 = (const float*)d_in[21];
    const float* cg2 = (const float*)d_in[22];
    const float* cb2 = (const float*)d_in[23];
    const float* cWo = (const float*)d_in[24];
    const float* cbo = (const float*)d_in[25];

    float *s1, *s3, *s4, *s5;
    cudaGetSymbolAddress((void**)&s1, S1);
    cudaGetSymbolAddress((void**)&s3, S3);
    cudaGetSymbolAddress((void**)&s4, S4);
    cudaGetSymbolAddress((void**)&s5, S5);

    const int N = in_sizes[0] / 128;       // 100000
    const int M = N * 6;
    const int gN = (N + 127) / 128, gM = (M + 127) / 128;
    float* out   = (float*)d_out;
    float* regO  = out + (size_t)N * 6;
    float* feats = regO + (size_t)N * 360;

    const size_t shM = (size_t)(128 * SA + 16384 + 3 * 128 + 256 + 3 * 128) * 4;
    const size_t shW = (size_t)(128 * SA + 128 * 64 + 64) * 4;
    cudaFuncSetAttribute(gemm_k,  cudaFuncAttributeMaxDynamicSharedMemorySize, (int)shM);
    cudaFuncSetAttribute(gemm_wo, cudaFuncAttributeMaxDynamicSharedMemorySize, (int)shW);

    dim3 blk(256);
    GP q;

    // L1: actB = actors @ agt_W[128:256]  -> S5
    q = GP{}; q.A = actors; q.W = aW + 128 * 128; q.out = s5; q.M = N;
    gemm_k<<<dim3(gN, 1), blk, shM>>>(q);

    // L2: h1 = relu(gn(actors @ pred_W1))  -> S1 (mode-major), all 6 modes
    q = GP{}; q.A = actors; q.W = pW1; q.W_k = 16384;
    q.g = pg1; q.b = pb1; q.gb_k = 128;
    q.out = s1; q.out_k = (i64)N * 128; q.M = N; q.gn = 1; q.relu = 1;
    gemm_k<<<dim3(gN, 6), blk, shM>>>(q);

    // L3: h = relu(gn(h1 @ pred_W2) + actors)  -> S1 in-place
    q = GP{}; q.A = s1; q.A_k = (i64)N * 128; q.W = pW2; q.W_k = 16384;
    q.g = pg2; q.b = pb2; q.gb_k = 128;
    q.out = s1; q.out_k = (i64)N * 128; q.post = actors; q.M = N; q.gn = 1; q.relu = 1;
    gemm_k<<<dim3(gN, 6), blk, shM>>>(q);

    // L4: preds = h @ pred_Wo + bo  -> S3 [n][k][60]
    gemm_wo<<<dim3(gN, 6), blk, shW>>>(s1, (i64)N * 128, pWo, 128 * 60, pbo, s3, N);

    // L5: dh2 = relu(gn(gen(dh) @ dist_W1))  -> S1 [M,128]
    q = GP{}; q.genP = s3; q.W0 = dW0; q.b0 = db0; q.W = dW1;
    q.g = dg1; q.b = db1; q.out = s1; q.M = M; q.gn = 1; q.relu = 1;
    gemm_k<<<dim3(gM, 1), blk, shM>>>(q);

    // L6: feats = relu(gn(dh2 @ agt_W[0:128] + actB[n]))  -> d_out feats region
    q = GP{}; q.A = s1; q.W = aW; q.g = ag; q.b = ab; q.pre = s5;
    q.out = feats; q.M = M; q.gn = 1; q.relu = 1;
    gemm_k<<<dim3(gM, 1), blk, shM>>>(q);

    // L7: c1 = relu(gn(feats @ cls_W1))  -> S1
    q = GP{}; q.A = feats; q.W = cW1; q.g = cg1; q.b = cb1;
    q.out = s1; q.M = M; q.gn = 1; q.relu = 1;
    gemm_k<<<dim3(gM, 1), blk, shM>>>(q);

    // L8: c = relu(gn(c1 @ cls_W2) + feats); logits = c @ cls_Wo + bo -> S4
    q = GP{}; q.A = s1; q.W = cW2; q.g = cg2; q.b = cb2;
    q.post = feats; q.wo = cWo; q.wob = cbo; q.dot = s4;
    q.M = M; q.gn = 1; q.relu = 1;
    gemm_k<<<dim3(gM, 1), blk, shM>>>(q);

    // L9: softmax + sort + gather
    finalize<<<(N + 7) / 8, blk>>>(s3, s4, ctrs, out, regO, N);
}

// round 5
// speedup vs baseline: 1.4467x; 1.4467x over previous
#include <cuda_runtime.h>
#include <cuda_bf16.h>
#include <cstdint>

typedef unsigned long long u64;
typedef long long i64;
typedef uint32_t u32;

#define EPS 1e-5f

// ---------------- scratch (device globals; no runtime alloc) ----------------
__device__ __align__(16) u32   S1[600000u * 128];   // packed bf16-split activations
__device__ __align__(16) u32   S2[600000u * 128];
__device__ __align__(16) float S3[600000u * 60];    // preds [n][k][60]
__device__ __align__(16) float S4[600000];          // cls logits
__device__ __align__(16) float S5[100000u * 128];   // actors @ agt_W[128:256] (fp32)
__device__ __align__(16) u32   XP[100000u * 128];   // actors packed
__device__ __align__(16) __nv_bfloat16 WIMG[17 * 32768];  // per matrix: hi plane [n][k] 16384 + lo plane

// ---------------- helpers ----------------------------------------------------
__device__ __forceinline__ u32 packbf(float x) {
    u32 hb = (u32)__bfloat16_as_ushort(__float2bfloat16(x));
    float r = x - __uint_as_float(hb << 16);
    return (hb << 16) | (u32)__bfloat16_as_ushort(__float2bfloat16(r));
}
__device__ __forceinline__ float unpackf(u32 w) {
    return __uint_as_float(w & 0xffff0000u) + __uint_as_float(w << 16);
}
__device__ __forceinline__ void mma16816(float* c, const u32* a, const u32* b) {
    asm volatile(
        "mma.sync.aligned.m16n8k16.row.col.f32.bf16.bf16.f32 "
        "{%0,%1,%2,%3}, {%4,%5,%6,%7}, {%8,%9}, {%0,%1,%2,%3};"
        : "+f"(c[0]), "+f"(c[1]), "+f"(c[2]), "+f"(c[3])
        : "r"(a[0]), "r"(a[1]), "r"(a[2]), "r"(a[3]), "r"(b[0]), "r"(b[1]));
}

// ---------------- weight prep: transpose + split ----------------------------
// Output per matrix id: hi plane [n][k] bf16 (16384), then lo plane (16384).
__global__ void prep_w(const float* pW1, const float* pW2, const float* dW1,
                       const float* aW, const float* cW1, const float* cW2)
{
    int id = blockIdx.x;
    const float* W;
    if      (id < 6)   W = pW1 + id * 16384;
    else if (id < 12)  W = pW2 + (id - 6) * 16384;
    else if (id == 12) W = dW1;
    else if (id == 13) W = aW;               // agt_W rows 0..127
    else if (id == 14) W = aW + 16384;       // agt_W rows 128..255
    else if (id == 15) W = cW1;
    else               W = cW2;
    __nv_bfloat16* hi = WIMG + id * 32768;
    __nv_bfloat16* lo = hi + 16384;
    for (int idx = threadIdx.x; idx < 16384; idx += blockDim.x) {
        int n = idx >> 7, k = idx & 127;
        float x = W[k * 128 + n];            // B[n][k] = W[k][n]
        __nv_bfloat16 h = __float2bfloat16(x);
        float r = x - __uint_as_float(((u32)__bfloat16_as_ushort(h)) << 16);
        hi[idx] = h;
        lo[idx] = __float2bfloat16(r);
    }
}

__global__ void prep_x(const float* a, u32* dst, int n) {
    int i = blockIdx.x * blockDim.x + threadIdx.x;
    if (i < n) dst[i] = packbf(a[i]);
}

// ---------------- main tensor GEMM: out = epi(A[M,128] @ W[128,128]) --------
struct TGP {
    const u32* A;  i64 A_k;                 // packed activations (u32 elems)
    const __nv_bfloat16* Wimg; i64 W_k;     // prep'd planes (bf16 elems)
    const float* g; const float* b; i64 gb_k;
    float* outF; i64 outF_k;
    u32* outP;   i64 outP_k;
    const float* pre;                       // pre-GN add, row = grow/6
    const float* post; i64 post_k;          // post-GN add, row = grow
    const float* wo; const float* wob; float* dot;
    const float* genP; const float* W0; const float* b0;   // dist A-gen
    int M, gn, relu;
};

// smem bytes: 4096 vectors | Ahi 34816 | Alo 34816 | Whi 34816 | Wlo 34816
#define RS 272                      // row stride bytes (136 bf16)
#define OF_AH 4096
#define OF_AL (OF_AH + 34816)
#define OF_WH (OF_AL + 34816)
#define OF_WL (OF_WH + 34816)
#define TG_SMEM (OF_WL + 34816)
#define CSTR 132                    // C float stride (overlays A region)

__global__ void __launch_bounds__(256, 1) tgemm(TGP p) {
    extern __shared__ char smc[];
    float* gv  = (float*)smc;
    float* bv  = gv + 128;
    float* wv  = bv + 128;
    float* w0a = wv + 128;
    float* w0b = w0a + 128;
    float* b0v = w0b + 128;
    float* pav = b0v + 128;
    float* pbv = pav + 128;
    char* Ahi = smc + OF_AH;
    char* Alo = smc + OF_AL;
    char* Whi = smc + OF_WH;
    char* Wlo = smc + OF_WL;
    float* Cs = (float*)(smc + OF_AH);      // overlays A after MMA

    const int tid = threadIdx.x, wid = tid >> 5, lane = tid & 31;
    const int y = blockIdx.y;
    const int row0 = blockIdx.x * 128;

    // ---- stage W planes (global [n][k] stride 128 -> smem stride 136) ----
    {
        const uint4* src = (const uint4*)(p.Wimg + (size_t)p.W_k * y);
        #pragma unroll
        for (int i = 0; i < 16; i++) {
            int idx = tid + 256 * i;              // 4096 uint4 total (2 planes)
            int plane = idx >> 11, rem = idx & 2047;
            int r = rem >> 4, c = rem & 15;
            char* dst = (plane ? Wlo : Whi) + r * RS + c * 16;
            *(uint4*)dst = src[idx];
        }
    }
    if (tid < 128) {
        if (p.gn) { gv[tid] = p.g[p.gb_k * y + tid]; bv[tid] = p.b[p.gb_k * y + tid]; }
        if (p.wo) wv[tid] = p.wo[tid];
    }

    // ---- stage A planes ----
    if (p.genP) {
        if (tid < 128) {
            w0a[tid] = p.W0[tid]; w0b[tid] = p.W0[128 + tid]; b0v[tid] = p.b0[tid];
            int gr = row0 + tid; float a = 0.f, bq = 0.f;
            if (gr < p.M) { a = p.genP[(size_t)gr * 60 + 58]; bq = p.genP[(size_t)gr * 60 + 59]; }
            pav[tid] = a; pbv[tid] = bq;
        }
        __syncthreads();
        for (int idx = tid; idx < 16384; idx += 256) {
            int r = idx >> 7, k = idx & 127;
            float x = fmaxf(b0v[k] - pav[r] * w0a[k] - pbv[r] * w0b[k], 0.f);
            __nv_bfloat16 h = __float2bfloat16(x);
            float rr = x - __uint_as_float(((u32)__bfloat16_as_ushort(h)) << 16);
            *(__nv_bfloat16*)(Ahi + r * RS + k * 2) = h;
            *(__nv_bfloat16*)(Alo + r * RS + k * 2) = __float2bfloat16(rr);
        }
    } else {
        const u32* Ag = p.A + (size_t)p.A_k * y;
        #pragma unroll
        for (int i = 0; i < 16; i++) {
            int idx = tid + 256 * i;              // 4096 uint4 (rows x 32)
            int r = idx >> 5, c = idx & 31;       // c: uint4 within row (4 packed vals)
            int gr = row0 + r;
            uint4 v = make_uint4(0u, 0u, 0u, 0u);
            if (gr < p.M) v = ((const uint4*)(Ag + (size_t)gr * 128))[c];
            u32 h01 = __byte_perm(v.x, v.y, 0x7632), h23 = __byte_perm(v.z, v.w, 0x7632);
            u32 l01 = __byte_perm(v.x, v.y, 0x5410), l23 = __byte_perm(v.z, v.w, 0x5410);
            int off = r * RS + c * 8;             // 4 bf16 = 8 bytes
            *(uint2*)(Ahi + off) = make_uint2(h01, h23);
            *(uint2*)(Alo + off) = make_uint2(l01, l23);
        }
    }
    __syncthreads();

    // ---- MMA: 8 warps, 2x4 grid, warp tile 64 rows x 32 cols ----
    const int wm = wid >> 2, wn = wid & 3;
    const int g = lane >> 2, tg = lane & 3;
    float acc[4][4][4];
    #pragma unroll
    for (int i = 0; i < 4; i++)
        #pragma unroll
        for (int j = 0; j < 4; j++)
            #pragma unroll
            for (int q = 0; q < 4; q++) acc[i][j][q] = 0.f;

    #pragma unroll
    for (int ks = 0; ks < 8; ks++) {
        const int k0 = ks * 16;
        const int cA = (k0 + tg * 2) * 2;         // byte col
        u32 ah[4][4], al[4][4];
        #pragma unroll
        for (int mt = 0; mt < 4; mt++) {
            int rb = (wm * 64 + mt * 16 + g) * RS;
            ah[mt][0] = *(const u32*)(Ahi + rb + cA);
            ah[mt][1] = *(const u32*)(Ahi + rb + 8 * RS + cA);
            ah[mt][2] = *(const u32*)(Ahi + rb + cA + 16);
            ah[mt][3] = *(const u32*)(Ahi + rb + 8 * RS + cA + 16);
            al[mt][0] = *(const u32*)(Alo + rb + cA);
            al[mt][1] = *(const u32*)(Alo + rb + 8 * RS + cA);
            al[mt][2] = *(const u32*)(Alo + rb + cA + 16);
            al[mt][3] = *(const u32*)(Alo + rb + 8 * RS + cA + 16);
        }
        u32 bh[4][2], bl[4][2];
        #pragma unroll
        for (int nt = 0; nt < 4; nt++) {
            int nb = (wn * 32 + nt * 8 + g) * RS;
            bh[nt][0] = *(const u32*)(Whi + nb + cA);
            bh[nt][1] = *(const u32*)(Whi + nb + cA + 16);
            bl[nt][0] = *(const u32*)(Wlo + nb + cA);
            bl[nt][1] = *(const u32*)(Wlo + nb + cA + 16);
        }
        #pragma unroll
        for (int mt = 0; mt < 4; mt++)
            #pragma unroll
            for (int nt = 0; nt < 4; nt++) {
                mma16816(acc[mt][nt], ah[mt], bh[nt]);
                mma16816(acc[mt][nt], al[mt], bh[nt]);
                mma16816(acc[mt][nt], ah[mt], bl[nt]);
            }
    }
    __syncthreads();   // A region dead; reuse as C

    #pragma unroll
    for (int mt = 0; mt < 4; mt++) {
        int r0 = wm * 64 + mt * 16 + g;
        #pragma unroll
        for (int nt = 0; nt < 4; nt++) {
            int c0 = wn * 32 + nt * 8 + tg * 2;
            *(float2*)(Cs + (size_t)r0 * CSTR + c0)       = make_float2(acc[mt][nt][0], acc[mt][nt][1]);
            *(float2*)(Cs + (size_t)(r0 + 8) * CSTR + c0) = make_float2(acc[mt][nt][2], acc[mt][nt][3]);
        }
    }
    __syncthreads();

    // ---- epilogue: 128 threads, one full row each ----
    if (tid < 128) {
        float v[128];
        const float4* cr = (const float4*)(Cs + (size_t)tid * CSTR);
        #pragma unroll
        for (int j = 0; j < 32; j++) {
            float4 a = cr[j];
            v[4*j] = a.x; v[4*j+1] = a.y; v[4*j+2] = a.z; v[4*j+3] = a.w;
        }
        const int grow = row0 + tid;
        const bool ok = grow < p.M;

        if (p.pre && ok) {
            const float4* q = (const float4*)(p.pre + (size_t)(grow / 6) * 128);
            #pragma unroll
            for (int j = 0; j < 32; j++) {
                float4 a = q[j];
                v[4*j] += a.x; v[4*j+1] += a.y; v[4*j+2] += a.z; v[4*j+3] += a.w;
            }
        }
        if (p.gn) {
            float s = 0.f, q = 0.f;
            #pragma unroll
            for (int j = 0; j < 128; j++) { s += v[j]; q += v[j] * v[j]; }
            float m = s * (1.f / 128.f);
            float inv = rsqrtf(q * (1.f / 128.f) - m * m + EPS);
            #pragma unroll
            for (int j = 0; j < 128; j++) v[j] = (v[j] - m) * inv * gv[j] + bv[j];
        }
        if (p.post && ok) {
            const float4* q = (const float4*)(p.post + p.post_k * y + (size_t)grow * 128);
            #pragma unroll
            for (int j = 0; j < 32; j++) {
                float4 a = q[j];
                v[4*j] += a.x; v[4*j+1] += a.y; v[4*j+2] += a.z; v[4*j+3] += a.w;
            }
        }
        if (p.relu) {
            #pragma unroll
            for (int j = 0; j < 128; j++) v[j] = fmaxf(v[j], 0.f);
        }
        if (p.wo && ok) {
            float d = 0.f;
            #pragma unroll
            for (int j = 0; j < 128; j++) d += v[j] * wv[j];
            p.dot[grow] = d + p.wob[0];
        }
        if (p.outF && ok) {
            float4* d = (float4*)(p.outF + p.outF_k * y + (size_t)grow * 128);
            #pragma unroll
            for (int j = 0; j < 32; j++) d[j] = make_float4(v[4*j], v[4*j+1], v[4*j+2], v[4*j+3]);
        }
        if (p.outP && ok) {
            uint4* d = (uint4*)(p.outP + p.outP_k * y + (size_t)grow * 128);
            #pragma unroll
            for (int j = 0; j < 32; j++)
                d[j] = make_uint4(packbf(v[4*j]), packbf(v[4*j+1]), packbf(v[4*j+2]), packbf(v[4*j+3]));
        }
    }
}

// ---------------- Wo head (FFMA2): [M,128] @ [128,60] + bias ----------------
#define SAW 130
__device__ __forceinline__ void fma2(u64& d, u64 a, u64 b) {
    asm("fma.rn.f32x2 %0, %1, %2, %0;" : "+l"(d) : "l"(a), "l"(b));
}
__device__ __forceinline__ u64 pk(float x) {
    u64 r; asm("mov.b64 %0, {%1, %1};" : "=l"(r) : "f"(x)); return r;
}
__device__ __forceinline__ void up2(float& lo, float& hi, u64 v) {
    asm("mov.b64 {%0, %1}, %2;" : "=f"(lo), "=f"(hi) : "l"(v));
}

__global__ void __launch_bounds__(256, 1) gemm_wo(
    const u32* A, i64 A_k, const float* W, i64 W_k,
    const float* bo, float* out, int M)
{
    extern __shared__ float sm[];
    float* As = sm;               // [128][SAW] transposed fp32 A tile
    float* Ws = As + 128 * SAW;   // [128][64]
    float* bb = Ws + 128 * 64;

    const int tid = threadIdx.x, y = blockIdx.y, row0 = blockIdx.x * 128;
    const float* Wg = W + W_k * y;
    out += y * 60;

    for (int idx = tid; idx < 128 * 64; idx += 256) {
        int r = idx >> 6, c = idx & 63;
        Ws[idx] = (c < 60) ? Wg[r * 60 + c] : 0.f;
    }
    if (tid < 64) bb[tid] = (tid < 60) ? bo[y * 60 + tid] : 0.f;

    const u32* Ag = A + (size_t)A_k * y;
    #pragma unroll
    for (int it = 0; it < 16; it++) {
        int idx = tid + it * 256;
        int r = idx >> 5, c4 = (idx & 31) * 4, gr = row0 + r;
        uint4 w = make_uint4(0u, 0u, 0u, 0u);
        if (gr < M) w = ((const uint4*)(Ag + (size_t)gr * 128))[idx & 31];
        As[(c4    ) * SAW + r] = unpackf(w.x);
        As[(c4 + 1) * SAW + r] = unpackf(w.y);
        As[(c4 + 2) * SAW + r] = unpackf(w.z);
        As[(c4 + 3) * SAW + r] = unpackf(w.w);
    }
    __syncthreads();

    const int rg = tid >> 4, cg = tid & 15;
    u64 acc[4][4];
    #pragma unroll
    for (int i = 0; i < 4; i++)
        #pragma unroll
        for (int j = 0; j < 4; j++) acc[i][j] = 0ull;

    #pragma unroll 4
    for (int k = 0; k < 128; k++) {
        const u64* ap = (const u64*)(As + k * SAW + rg * 8);
        u64 a0 = ap[0], a1 = ap[1], a2 = ap[2], a3 = ap[3];
        float4 q = *(const float4*)(Ws + k * 64 + cg * 4);
        u64 b0 = pk(q.x), b1 = pk(q.y), b2 = pk(q.z), b3 = pk(q.w);
        fma2(acc[0][0], a0, b0); fma2(acc[0][1], a0, b1); fma2(acc[0][2], a0, b2); fma2(acc[0][3], a0, b3);
        fma2(acc[1][0], a1, b0); fma2(acc[1][1], a1, b1); fma2(acc[1][2], a1, b2); fma2(acc[1][3], a1, b3);
        fma2(acc[2][0], a2, b0); fma2(acc[2][1], a2, b1); fma2(acc[2][2], a2, b2); fma2(acc[2][3], a2, b3);
        fma2(acc[3][0], a3, b0); fma2(acc[3][1], a3, b1); fma2(acc[3][2], a3, b2); fma2(acc[3][3], a3, b3);
    }

    #pragma unroll
    for (int i = 0; i < 4; i++) {
        int rl = row0 + rg * 8 + 2 * i, rh = rl + 1;
        #pragma unroll
        for (int j = 0; j < 4; j++) {
            int c = cg * 4 + j;
            float lo, hi; up2(lo, hi, acc[i][j]);
            if (c < 60) {
                if (rl < M) out[(size_t)rl * 360 + c] = lo + bb[c];
                if (rh < M) out[(size_t)rh * 360 + c] = hi + bb[c];
            }
        }
    }
}

// ---------------- softmax + rank-sort + reg gather (warp per actor) ---------
__global__ void finalize(const float* preds, const float* lg, const float* ctr,
                         float* clsO, float* regO, int N)
{
    int w = (blockIdx.x * blockDim.x + threadIdx.x) >> 5;
    int lane = threadIdx.x & 31;
    if (w >= N) return;
    float v = (lane < 6) ? lg[(size_t)w * 6 + lane] : -3.4e38f;
    float m = v;
    #pragma unroll
    for (int s = 4; s >= 1; s >>= 1) m = fmaxf(m, __shfl_xor_sync(~0u, m, s));
    float e = (lane < 6) ? expf(v - m) : 0.f;
    float s = e;
    #pragma unroll
    for (int t = 4; t >= 1; t >>= 1) s += __shfl_xor_sync(~0u, s, t);
    float pr = e / s;
    int rk = 0;
    #pragma unroll
    for (int j = 0; j < 6; j++) {
        float pj = __shfl_sync(~0u, pr, j);
        rk += (pj > pr) || (pj == pr && j < lane);
    }
    if (lane < 6) clsO[(size_t)w * 6 + rk] = pr;
    float cx = ctr[(size_t)w * 2], cy = ctr[(size_t)w * 2 + 1];
    for (int k = 0; k < 6; k++) {
        int r = __shfl_sync(~0u, rk, k);
        const float* sp = preds + (size_t)w * 360 + k * 60;
        float* dp = regO + ((size_t)w * 6 + r) * 60;
        for (int j = lane; j < 60; j += 32) dp[j] = sp[j] + ((j & 1) ? cy : cx);
    }
}

// ---------------- host orchestration ----------------------------------------
extern "C" void kernel_launch(void* const* d_in, const int* in_sizes, int n_in,
                              void* d_out, int out_size)
{
    const float* actors = (const float*)d_in[0];
    const float* ctrs   = (const float*)d_in[1];
    const float* pW1 = (const float*)d_in[2];
    const float* pg1 = (const float*)d_in[3];
    const float* pb1 = (const float*)d_in[4];
    const float* pW2 = (const float*)d_in[5];
    const float* pg2 = (const float*)d_in[6];
    const float* pb2 = (const float*)d_in[7];
    const float* pWo = (const float*)d_in[8];
    const float* pbo = (const float*)d_in[9];
    const float* dW0 = (const float*)d_in[10];
    const float* db0 = (const float*)d_in[11];
    const float* dW1 = (const float*)d_in[12];
    const float* dg1 = (const float*)d_in[13];
    const float* db1 = (const float*)d_in[14];
    const float* aW  = (const float*)d_in[15];
    const float* ag  = (const float*)d_in[16];
    const float* ab  = (const float*)d_in[17];
    const float* cW1 = (const float*)d_in[18];
    const float* cg1 = (const float*)d_in[19];
    const float* cb1 = (const float*)d_in[20];
    const float* cW2 = (const float*)d_in[21];
    const float* cg2 = (const float*)d_in[22];
    const float* cb2 = (const float*)d_in[23];
    const float* cWo = (const float*)d_in[24];
    const float* cbo = (const float*)d_in[25];

    u32 *s1, *s2, *xp; float *s3, *s4, *s5; __nv_bfloat16* wimg;
    cudaGetSymbolAddress((void**)&s1, S1);
    cudaGetSymbolAddress((void**)&s2, S2);
    cudaGetSymbolAddress((void**)&s3, S3);
    cudaGetSymbolAddress((void**)&s4, S4);
    cudaGetSymbolAddress((void**)&s5, S5);
    cudaGetSymbolAddress((void**)&xp, XP);
    cudaGetSymbolAddress((void**)&wimg, WIMG);

    const int N = in_sizes[0] / 128;       // 100000
    const int M = N * 6;
    const int gN = (N + 127) / 128, gM = (M + 127) / 128;
    float* out   = (float*)d_out;
    float* regO  = out + (size_t)N * 6;
    float* feats = regO + (size_t)N * 360;

    cudaFuncSetAttribute(tgemm, cudaFuncAttributeMaxDynamicSharedMemorySize, TG_SMEM);
    const size_t shW = (size_t)(128 * SAW + 128 * 64 + 64) * 4;
    cudaFuncSetAttribute(gemm_wo, cudaFuncAttributeMaxDynamicSharedMemorySize, (int)shW);

    prep_w<<<17, 128>>>(pW1, pW2, dW1, aW, cW1, cW2);
    prep_x<<<(N * 128 + 255) / 256, 256>>>(actors, xp, N * 128);

    TGP q;

    // L1: actB = actors @ agt_W[128:256] -> S5 fp32
    q = TGP{}; q.A = xp; q.Wimg = wimg + 14 * 32768; q.outF = s5; q.M = N;
    tgemm<<<dim3(gN, 1), 256, TG_SMEM>>>(q);

    // L2: h1 = relu(gn(actors @ pred_W1)) -> S1 packed (mode-major)
    q = TGP{}; q.A = xp; q.Wimg = wimg; q.W_k = 32768;
    q.g = pg1; q.b = pb1; q.gb_k = 128;
    q.outP = s1; q.outP_k = (i64)N * 128; q.M = N; q.gn = 1; q.relu = 1;
    tgemm<<<dim3(gN, 6), 256, TG_SMEM>>>(q);

    // L3: h = relu(gn(h1 @ pred_W2) + actors) -> S1 in-place
    q = TGP{}; q.A = s1; q.A_k = (i64)N * 128; q.Wimg = wimg + 6 * 32768; q.W_k = 32768;
    q.g = pg2; q.b = pb2; q.gb_k = 128; q.post = actors;
    q.outP = s1; q.outP_k = (i64)N * 128; q.M = N; q.gn = 1; q.relu = 1;
    tgemm<<<dim3(gN, 6), 256, TG_SMEM>>>(q);

    // L4: preds = h @ pred_Wo + bo -> S3 [n][k][60]
    gemm_wo<<<dim3(gN, 6), 256, shW>>>(s1, (i64)N * 128, pWo, 128 * 60, pbo, s3, N);

    // L5: dh2 = relu(gn(gen(dist) @ dist_W1)) -> S1 packed [M]
    q = TGP{}; q.genP = s3; q.W0 = dW0; q.b0 = db0; q.Wimg = wimg + 12 * 32768;
    q.g = dg1; q.b = db1; q.outP = s1; q.M = M; q.gn = 1; q.relu = 1;
    tgemm<<<dim3(gM, 1), 256, TG_SMEM>>>(q);

    // L6: feats = relu(gn(dh2 @ agt_W[0:128] + actB)) -> feats fp32 + S2 packed
    q = TGP{}; q.A = s1; q.Wimg = wimg + 13 * 32768; q.g = ag; q.b = ab; q.pre = s5;
    q.outF = feats; q.outP = s2; q.M = M; q.gn = 1; q.relu = 1;
    tgemm<<<dim3(gM, 1), 256, TG_SMEM>>>(q);

    // L7: c1 = relu(gn(feats @ cls_W1)) -> S1 packed
    q = TGP{}; q.A = s2; q.Wimg = wimg + 15 * 32768; q.g = cg1; q.b = cb1;
    q.outP = s1; q.M = M; q.gn = 1; q.relu = 1;
    tgemm<<<dim3(gM, 1), 256, TG_SMEM>>>(q);

    // L8: c = relu(gn(c1 @ cls_W2) + feats); logits = c @ cls_Wo + cbo -> S4
    q = TGP{}; q.A = s1; q.Wimg = wimg + 16 * 32768; q.g = cg2; q.b = cb2;
    q.post = feats; q.wo = cWo; q.wob = cbo; q.dot = s4; q.M = M; q.gn = 1; q.relu = 1;
    tgemm<<<dim3(gM, 1), 256, TG_SMEM>>>(q);

    // L9: softmax + sort + gather
    finalize<<<(N + 7) / 8, 256>>>(s3, s4, ctrs, out, regO, N);
}